// round 1
// baseline (speedup 1.0000x reference)
#include <cuda_runtime.h>
#include <math.h>

#define HD 128
#define M_MAX 2048
#define J_MAX 8192
#define N_MAX 262144
#define RED_BLOCKS 256

// ---------------- device scratch (no allocations allowed) ----------------
__device__ float  g_g0[HD];            // x_graph @ W0[0:256] + b0
__device__ float  g_A[M_MAX * HD];     // x_m    @ W0[256:384]
__device__ float  g_B[J_MAX * HD];     // x_job  @ W0[384:512]
__device__ float  g_scores[N_MAX];
__device__ float  g_bmax[RED_BLOCKS];
__device__ int    g_barg[RED_BLOCKS];
__device__ float  g_max;
__device__ int    g_arg;
__device__ double g_Z;
__device__ double g_S;

// ---------------- packed f32x2 helpers (Blackwell dual-FP32 pipe) --------
__device__ __forceinline__ unsigned long long pack2(float x, float y) {
    unsigned long long r;
    asm("mov.b64 %0, {%1, %2};" : "=l"(r) : "f"(x), "f"(y));
    return r;
}
__device__ __forceinline__ void fma2acc(unsigned long long& d,
                                        unsigned long long a,
                                        unsigned long long b) {
    asm("fma.rn.f32x2 %0, %1, %2, %0;" : "+l"(d) : "l"(a), "l"(b));
}
__device__ __forceinline__ float2 unpack2(unsigned long long v) {
    float2 f;
    asm("mov.b64 {%0, %1}, %2;" : "=f"(f.x), "=f"(f.y) : "l"(v));
    return f;
}

// ---------------- precompute: g0 = b0 + x_graph @ W0[0:256] --------------
__global__ void k_g0(const float* __restrict__ xg,
                     const float* __restrict__ W0,
                     const float* __restrict__ b0) {
    __shared__ float xs[256];
    int j = threadIdx.x;                 // 128 threads
    xs[j]       = xg[j];
    xs[j + 128] = xg[j + 128];
    __syncthreads();
    float s = b0[j];
#pragma unroll 8
    for (int k = 0; k < 256; k++) s = fmaf(xs[k], W0[k * HD + j], s);
    g_g0[j] = s;
}

// ------------- precompute: embed tables  out = X @ W0slab ----------------
// which==0 -> g_A, which==1 -> g_B.  128 threads, 8 rows per block.
__global__ void k_embed(const float* __restrict__ X,
                        const float* __restrict__ W0slab,
                        int rows, int which) {
    extern __shared__ float sh[];
    float* W0s = sh;             // 16384 floats
    float* xs  = sh + 16384;     // 8*128 floats
    float* out = which ? g_B : g_A;
    int tid = threadIdx.x;
    for (int i = tid; i < 16384; i += 128) W0s[i] = W0slab[i];
    int base = blockIdx.x * 8;
#pragma unroll
    for (int r = 0; r < 8; r++) {
        int row = base + r;
        xs[r * 128 + tid] = (row < rows) ? X[row * 128 + tid] : 0.f;
    }
    __syncthreads();
    float acc[8] = {0.f, 0.f, 0.f, 0.f, 0.f, 0.f, 0.f, 0.f};
#pragma unroll 4
    for (int k = 0; k < 128; k++) {
        float w = W0s[k * 128 + tid];
#pragma unroll
        for (int r = 0; r < 8; r++) acc[r] = fmaf(xs[r * 128 + k], w, acc[r]);
    }
#pragma unroll
    for (int r = 0; r < 8; r++) {
        int row = base + r;
        if (row < rows) out[row * 128 + tid] = acc[r];
    }
}

// ---------------- main fused MLP kernel ----------------------------------
// per warp: 4 rows/group. h1 = relu(g0 + A[m] + B[j]); pre1 = h1 @ W1 (+b1);
// score = relu(pre1) . W2 + b2
__global__ void __launch_bounds__(256)
k_main(const int* __restrict__ m_ids, const int* __restrict__ job_idx,
       const float* __restrict__ W1, const float* __restrict__ b1,
       const float* __restrict__ W2, const float* __restrict__ b2, int N) {
    extern __shared__ float sh[];
    float* W1s = sh;              // 16384
    float* h1s = sh + 16384;      // 8 warps * 4 rows * 128 = 4096
    float* g0s = sh + 20480;      // 128
    float* b1s = sh + 20608;      // 128
    float* W2s = sh + 20736;      // 128

    int tid = threadIdx.x;
    for (int i = tid; i < 16384; i += 256) W1s[i] = W1[i];
    if (tid < 128) {
        g0s[tid] = g_g0[tid];
        b1s[tid] = b1[tid];
        W2s[tid] = W2[tid];
    }
    __syncthreads();

    int warp = tid >> 5, lane = tid & 31;
    float* h1w = h1s + warp * 512;
    const float4* W1s4 = (const float4*)W1s;

    float4 bb = ((const float4*)b1s)[lane];
    unsigned long long binit_lo = pack2(bb.x, bb.y);
    unsigned long long binit_hi = pack2(bb.z, bb.w);
    float4 gg = ((const float4*)g0s)[lane];
    float4 w2 = ((const float4*)W2s)[lane];
    float  bias2 = b2[0];

    int stride = gridDim.x * 8;
    for (int g = blockIdx.x * 8 + warp; g * 4 < N; g += stride) {
        int base = g * 4;
        int nr = N - base; if (nr > 4) nr = 4;

        // ---- layer 0: gather + add + relu into smem (per-warp buffer)
#pragma unroll
        for (int r = 0; r < 4; r++) {
            float4 h = make_float4(0.f, 0.f, 0.f, 0.f);
            if (r < nr) {
                int row = base + r;
                int m  = __ldg(&m_ids[row]);
                int jj = __ldg(&job_idx[row]);
                float4 a = *(const float4*)(g_A + m  * HD + lane * 4);
                float4 v = *(const float4*)(g_B + jj * HD + lane * 4);
                h.x = fmaxf(gg.x + a.x + v.x, 0.f);
                h.y = fmaxf(gg.y + a.y + v.y, 0.f);
                h.z = fmaxf(gg.z + a.z + v.z, 0.f);
                h.w = fmaxf(gg.w + a.w + v.w, 0.f);
            }
            *(float4*)(h1w + r * 128 + lane * 4) = h;
        }
        __syncwarp();

        // ---- layer 1: 128x128 GEMV x4 rows, packed dual-FP32 FMA
        unsigned long long acc[8];
#pragma unroll
        for (int r = 0; r < 4; r++) { acc[2 * r] = binit_lo; acc[2 * r + 1] = binit_hi; }

#pragma unroll 4
        for (int k = 0; k < 128; k++) {
            float4 w = W1s4[k * 32 + lane];
            unsigned long long wlo = pack2(w.x, w.y);
            unsigned long long whi = pack2(w.z, w.w);
            float h0 = h1w[k];
            float h1 = h1w[128 + k];
            float h2 = h1w[256 + k];
            float h3 = h1w[384 + k];
            unsigned long long hh;
            hh = pack2(h0, h0); fma2acc(acc[0], hh, wlo); fma2acc(acc[1], hh, whi);
            hh = pack2(h1, h1); fma2acc(acc[2], hh, wlo); fma2acc(acc[3], hh, whi);
            hh = pack2(h2, h2); fma2acc(acc[4], hh, wlo); fma2acc(acc[5], hh, whi);
            hh = pack2(h3, h3); fma2acc(acc[6], hh, wlo); fma2acc(acc[7], hh, whi);
        }

        // ---- layer 2 + warp reduction
#pragma unroll
        for (int r = 0; r < 4; r++) {
            if (r < nr) {
                float2 lo = unpack2(acc[2 * r]);
                float2 hi = unpack2(acc[2 * r + 1]);
                float p = fmaxf(lo.x, 0.f) * w2.x + fmaxf(lo.y, 0.f) * w2.y +
                          fmaxf(hi.x, 0.f) * w2.z + fmaxf(hi.y, 0.f) * w2.w;
#pragma unroll
                for (int off = 16; off > 0; off >>= 1)
                    p += __shfl_xor_sync(0xffffffffu, p, off);
                if (lane == 0) g_scores[base + r] = p + bias2;
            }
        }
    }
}

// ---------------- reduction 1: per-block max + argmax --------------------
__global__ void k_rmax(int N) {
    __shared__ float bm[256];
    __shared__ int   ba[256];
    int tid = threadIdx.x;
    float best = -3.402823466e38f;
    int bi = 0x7fffffff;
    for (int i = blockIdx.x * blockDim.x + tid; i < N; i += gridDim.x * blockDim.x) {
        float v = g_scores[i];
        if (v > best) { best = v; bi = i; }   // strictly-greater keeps first idx
    }
    bm[tid] = best; ba[tid] = bi;
    __syncthreads();
    for (int s = 128; s > 0; s >>= 1) {
        if (tid < s) {
            float ov = bm[tid + s]; int oi = ba[tid + s];
            if (ov > bm[tid] || (ov == bm[tid] && oi < ba[tid])) { bm[tid] = ov; ba[tid] = oi; }
        }
        __syncthreads();
    }
    if (tid == 0) { g_bmax[blockIdx.x] = bm[0]; g_barg[blockIdx.x] = ba[0]; }
}

// ---------------- reduction 2: final max + zero accumulators -------------
__global__ void k_rfin() {
    __shared__ float bm[256];
    __shared__ int   ba[256];
    int tid = threadIdx.x;
    bm[tid] = g_bmax[tid]; ba[tid] = g_barg[tid];
    __syncthreads();
    for (int s = 128; s > 0; s >>= 1) {
        if (tid < s) {
            float ov = bm[tid + s]; int oi = ba[tid + s];
            if (ov > bm[tid] || (ov == bm[tid] && oi < ba[tid])) { bm[tid] = ov; ba[tid] = oi; }
        }
        __syncthreads();
    }
    if (tid == 0) { g_max = bm[0]; g_arg = ba[0]; g_Z = 0.0; g_S = 0.0; }
}

// ---------------- reduction 3: Z = sum e, S = sum e*s (double) -----------
__global__ void k_rsum(int N) {
    __shared__ double zb[256];
    __shared__ double sb[256];
    int tid = threadIdx.x;
    double gm = (double)g_max;
    double z = 0.0, s = 0.0;
    for (int i = blockIdx.x * blockDim.x + tid; i < N; i += gridDim.x * blockDim.x) {
        double v = (double)g_scores[i];
        double e = exp(v - gm);
        z += e; s += e * v;
    }
    zb[tid] = z; sb[tid] = s;
    __syncthreads();
    for (int st = 128; st > 0; st >>= 1) {
        if (tid < st) { zb[tid] += zb[tid + st]; sb[tid] += sb[tid + st]; }
        __syncthreads();
    }
    if (tid == 0) { atomicAdd(&g_Z, zb[0]); atomicAdd(&g_S, sb[0]); }
}

// ---------------- finalize -----------------------------------------------
__global__ void k_final(float* out) {
    double Z = g_Z, S = g_S;
    double logZ = log(Z);
    out[0] = (float)g_arg;                         // idx
    out[1] = (float)exp(-logZ);                    // probs[idx] (s_idx == max)
    out[2] = (float)(-logZ);                       // logp[idx]
    out[3] = (float)((double)g_max + logZ - S / Z); // entropy
}

// ---------------- launch ---------------------------------------------------
extern "C" void kernel_launch(void* const* d_in, const int* in_sizes, int n_in,
                              void* d_out, int out_size) {
    const float* xg   = (const float*)d_in[0];
    const float* xm   = (const float*)d_in[1];
    const float* xj   = (const float*)d_in[2];
    const int*   mids = (const int*)  d_in[3];
    const int*   jidx = (const int*)  d_in[4];
    const float* W0   = (const float*)d_in[5];
    const float* b0   = (const float*)d_in[6];
    const float* W1   = (const float*)d_in[7];
    const float* b1   = (const float*)d_in[8];
    const float* W2   = (const float*)d_in[9];
    const float* b2   = (const float*)d_in[10];
    float* out = (float*)d_out;

    int N = in_sizes[3];
    int M = in_sizes[1] / HD;
    int J = in_sizes[2] / HD;
    if (N > N_MAX) N = N_MAX;
    if (M > M_MAX) M = M_MAX;
    if (J > J_MAX) J = J_MAX;

    const int embed_smem = (16384 + 8 * 128) * 4;     // 69632 B
    const int main_smem  = (16384 + 4096 + 3 * 128) * 4; // 83456 B
    cudaFuncSetAttribute(k_embed, cudaFuncAttributeMaxDynamicSharedMemorySize, embed_smem);
    cudaFuncSetAttribute(k_main,  cudaFuncAttributeMaxDynamicSharedMemorySize, main_smem);

    k_g0<<<1, 128>>>(xg, W0, b0);
    k_embed<<<(M + 7) / 8, 128, embed_smem>>>(xm, W0 + 256 * HD, M, 0);
    k_embed<<<(J + 7) / 8, 128, embed_smem>>>(xj, W0 + 384 * HD, J, 1);
    k_main<<<296, 256, main_smem>>>(mids, jidx, W1, b1, W2, b2, N);
    k_rmax<<<RED_BLOCKS, 256>>>(N);
    k_rfin<<<1, 256>>>();
    k_rsum<<<RED_BLOCKS, 256>>>(N);
    k_final<<<1, 1>>>(out);
    (void)n_in; (void)out_size;
}

// round 4
// speedup vs baseline: 1.0599x; 1.0599x over previous
#include <cuda_runtime.h>
#include <math.h>

#define HD 128
#define M_MAX 2048
#define J_MAX 8192
#define N_MAX 262144

// ---------------- device scratch (no allocations allowed) ----------------
__device__ float  g_g0[HD];            // x_graph @ W0[0:256] + b0
__device__ float  g_A[M_MAX * HD];     // x_m    @ W0[256:384]
__device__ float  g_B[J_MAX * HD];     // x_job  @ W0[384:512]
__device__ float  g_scores[N_MAX];
__device__ float  g_bmax[256];
__device__ int    g_barg[256];
__device__ float  g_max;
__device__ int    g_arg;
__device__ double g_Z;
__device__ double g_S;
__device__ unsigned int g_cnt1;
__device__ unsigned int g_cnt2;
__device__ int    g_flag;

// ---------------- packed f32x2 helpers (Blackwell dual-FP32 pipe) --------
__device__ __forceinline__ unsigned long long pack2(float x, float y) {
    unsigned long long r;
    asm("mov.b64 %0, {%1, %2};" : "=l"(r) : "f"(x), "f"(y));
    return r;
}
__device__ __forceinline__ unsigned long long packdup(float x) {
    unsigned long long r;
    asm("mov.b64 %0, {%1, %1};" : "=l"(r) : "f"(x));
    return r;
}
__device__ __forceinline__ void fma2acc(unsigned long long& d,
                                        unsigned long long a,
                                        unsigned long long b) {
    asm("fma.rn.f32x2 %0, %1, %2, %0;" : "+l"(d) : "l"(a), "l"(b));
}
__device__ __forceinline__ float2 unpack2(unsigned long long v) {
    float2 f;
    asm("mov.b64 {%0, %1}, %2;" : "=f"(f.x), "=f"(f.y) : "l"(v));
    return f;
}

// ======== k_pre: fused precompute (embeds + g0 + accumulator reset) ======
// blocks [0, bM)        : g_A = x_m  @ W0[256:384]
// blocks [bM, bM+bJ)    : g_B = x_job@ W0[384:512]
// block  bM+bJ          : g_g0 = b0 + x_graph @ W0[0:256]; reset counters
// 128 threads per block.
__global__ void k_pre(const float* __restrict__ xg,
                      const float* __restrict__ xm,
                      const float* __restrict__ xj,
                      const float* __restrict__ W0,
                      const float* __restrict__ b0,
                      int M, int J) {
    extern __shared__ float sh[];
    int bM = (M + 7) / 8;
    int bJ = (J + 7) / 8;
    int tid = threadIdx.x;

    if ((int)blockIdx.x >= bM + bJ) {
        // ---- g0 block
        __shared__ float xs[256];
        xs[tid]       = xg[tid];
        xs[tid + 128] = xg[tid + 128];
        __syncthreads();
        float s = b0[tid];
#pragma unroll 8
        for (int k = 0; k < 256; k++) s = fmaf(xs[k], W0[k * HD + tid], s);
        g_g0[tid] = s;
        if (tid == 0) {
            g_cnt1 = 0u; g_cnt2 = 0u; g_flag = 0;
            g_Z = 0.0; g_S = 0.0;
        }
        return;
    }

    // ---- embed blocks
    const float* X;
    const float* W0slab;
    float* out;
    int rows, blk;
    if ((int)blockIdx.x < bM) {
        X = xm; W0slab = W0 + 256 * HD; out = g_A; rows = M; blk = blockIdx.x;
    } else {
        X = xj; W0slab = W0 + 384 * HD; out = g_B; rows = J; blk = blockIdx.x - bM;
    }
    float* W0s = sh;             // 16384 floats
    float* xs  = sh + 16384;     // 8*128
    for (int i = tid; i < 16384; i += 128) W0s[i] = W0slab[i];
    int base = blk * 8;
#pragma unroll
    for (int r = 0; r < 8; r++) {
        int row = base + r;
        xs[r * 128 + tid] = (row < rows) ? X[row * 128 + tid] : 0.f;
    }
    __syncthreads();
    float acc[8] = {0.f, 0.f, 0.f, 0.f, 0.f, 0.f, 0.f, 0.f};
#pragma unroll 4
    for (int k = 0; k < 128; k++) {
        float w = W0s[k * 128 + tid];
#pragma unroll
        for (int r = 0; r < 8; r++) acc[r] = fmaf(xs[r * 128 + k], w, acc[r]);
    }
#pragma unroll
    for (int r = 0; r < 8; r++) {
        int row = base + r;
        if (row < rows) out[row * 128 + tid] = acc[r];
    }
}

// ======================= k_main: fused MLP =================================
// 8 warps/block, 8 rows/warp (64 rows per block-iteration).
// layer0: gather+add+relu -> smem; layer1: 128x128 GEMV with f32x2 FMA;
// layer2: dot W2 + warp shuffle reduce.
__global__ void __launch_bounds__(256, 2)
k_main(const int* __restrict__ m_ids, const int* __restrict__ job_idx,
       const float* __restrict__ W1, const float* __restrict__ b1,
       const float* __restrict__ W2, const float* __restrict__ b2, int N) {
    extern __shared__ float sh[];
    float* W1s = sh;              // 16384
    float* h1s = sh + 16384;      // 8 warps * 8 rows * 128 = 8192
    float* g0s = sh + 24576;      // 128
    float* b1s = sh + 24704;      // 128
    float* W2s = sh + 24832;      // 128

    int tid = threadIdx.x;
    {
        const float4* W1v = (const float4*)W1;
        float4* W1sv = (float4*)W1s;
        for (int i = tid; i < 4096; i += 256) W1sv[i] = W1v[i];
    }
    if (tid < 128) {
        g0s[tid] = g_g0[tid];
        b1s[tid] = b1[tid];
        W2s[tid] = W2[tid];
    }
    __syncthreads();

    int warp = tid >> 5, lane = tid & 31;
    float* h1w = h1s + warp * 1024;
    const float4* W1s4 = (const float4*)W1s;

    float4 bb = ((const float4*)b1s)[lane];
    unsigned long long binit_lo = pack2(bb.x, bb.y);
    unsigned long long binit_hi = pack2(bb.z, bb.w);
    float4 gg  = ((const float4*)g0s)[lane];
    float4 w2c = ((const float4*)W2s)[lane];
    float  bias2 = b2[0];

    int nchunk = (N + 63) >> 6;
    for (int c = blockIdx.x; c < nchunk; c += gridDim.x) {
        int base = c * 64 + warp * 8;

        // ---- layer 0: gather + add + relu into per-warp smem buffer
        __syncwarp();
#pragma unroll
        for (int r = 0; r < 8; r++) {
            int row = base + r;
            float4 h = make_float4(0.f, 0.f, 0.f, 0.f);
            if (row < N) {
                int m  = __ldg(&m_ids[row]);
                int jj = __ldg(&job_idx[row]);
                float4 a = *(const float4*)(g_A + m  * HD + lane * 4);
                float4 v = *(const float4*)(g_B + jj * HD + lane * 4);
                h.x = fmaxf(gg.x + a.x + v.x, 0.f);
                h.y = fmaxf(gg.y + a.y + v.y, 0.f);
                h.z = fmaxf(gg.z + a.z + v.z, 0.f);
                h.w = fmaxf(gg.w + a.w + v.w, 0.f);
            }
            *(float4*)(h1w + r * 128 + lane * 4) = h;
        }
        __syncwarp();

        // ---- layer 1: 8-row GEMV, packed dual-FP32 FMA
        unsigned long long acc[16];
#pragma unroll
        for (int r = 0; r < 8; r++) { acc[2 * r] = binit_lo; acc[2 * r + 1] = binit_hi; }

#pragma unroll 2
        for (int k4 = 0; k4 < 32; k4++) {
            float4 wa = W1s4[(k4 * 4 + 0) * 32 + lane];
            float4 wb = W1s4[(k4 * 4 + 1) * 32 + lane];
            float4 wc = W1s4[(k4 * 4 + 2) * 32 + lane];
            float4 wd = W1s4[(k4 * 4 + 3) * 32 + lane];
            unsigned long long wa_lo = pack2(wa.x, wa.y), wa_hi = pack2(wa.z, wa.w);
            unsigned long long wb_lo = pack2(wb.x, wb.y), wb_hi = pack2(wb.z, wb.w);
            unsigned long long wc_lo = pack2(wc.x, wc.y), wc_hi = pack2(wc.z, wc.w);
            unsigned long long wd_lo = pack2(wd.x, wd.y), wd_hi = pack2(wd.z, wd.w);
#pragma unroll
            for (int r = 0; r < 8; r++) {
                float4 h = *(const float4*)(h1w + r * 128 + k4 * 4);  // broadcast
                unsigned long long hh;
                hh = packdup(h.x); fma2acc(acc[2 * r], hh, wa_lo); fma2acc(acc[2 * r + 1], hh, wa_hi);
                hh = packdup(h.y); fma2acc(acc[2 * r], hh, wb_lo); fma2acc(acc[2 * r + 1], hh, wb_hi);
                hh = packdup(h.z); fma2acc(acc[2 * r], hh, wc_lo); fma2acc(acc[2 * r + 1], hh, wc_hi);
                hh = packdup(h.w); fma2acc(acc[2 * r], hh, wd_lo); fma2acc(acc[2 * r + 1], hh, wd_hi);
            }
        }

        // ---- layer 2 + warp reduction
#pragma unroll
        for (int r = 0; r < 8; r++) {
            int row = base + r;
            if (row < N) {
                float2 lo = unpack2(acc[2 * r]);
                float2 hi = unpack2(acc[2 * r + 1]);
                float p = fmaxf(lo.x, 0.f) * w2c.x + fmaxf(lo.y, 0.f) * w2c.y +
                          fmaxf(hi.x, 0.f) * w2c.z + fmaxf(hi.y, 0.f) * w2c.w;
#pragma unroll
                for (int off = 16; off > 0; off >>= 1)
                    p += __shfl_xor_sync(0xffffffffu, p, off);
                if (lane == 0) g_scores[row] = p + bias2;
            }
        }
    }
}

// ============ k_reduce: fused max/argmax -> softmax stats -> out ==========
// grid MUST be <= 148 blocks (all co-resident) : uses grid-wide spin sync.
__global__ void __launch_bounds__(256)
k_reduce(float* __restrict__ out, int N) {
    __shared__ float bm[256];
    __shared__ int   ba[256];
    __shared__ int   is_last;
    int tid = threadIdx.x;
    int nb  = gridDim.x;

    // ---- phase 1: max + argmax (first occurrence)
    float best = -3.402823466e38f;
    int   bi   = 0x7fffffff;
    for (int i = blockIdx.x * 256 + tid; i < N; i += nb * 256) {
        float v = g_scores[i];
        if (v > best) { best = v; bi = i; }
    }
    bm[tid] = best; ba[tid] = bi;
    __syncthreads();
    for (int s = 128; s > 0; s >>= 1) {
        if (tid < s) {
            float ov = bm[tid + s]; int oi = ba[tid + s];
            if (ov > bm[tid] || (ov == bm[tid] && oi < ba[tid])) { bm[tid] = ov; ba[tid] = oi; }
        }
        __syncthreads();
    }
    if (tid == 0) {
        g_bmax[blockIdx.x] = bm[0];
        g_barg[blockIdx.x] = ba[0];
        __threadfence();
        unsigned t = atomicAdd(&g_cnt1, 1u);
        is_last = (t == (unsigned)(nb - 1)) ? 1 : 0;
    }
    __syncthreads();

    if (is_last) {
        float v = (tid < nb) ? g_bmax[tid] : -3.402823466e38f;
        int   ii = (tid < nb) ? g_barg[tid] : 0x7fffffff;
        bm[tid] = v; ba[tid] = ii;
        __syncthreads();
        for (int s = 128; s > 0; s >>= 1) {
            if (tid < s) {
                float ov = bm[tid + s]; int oi = ba[tid + s];
                if (ov > bm[tid] || (ov == bm[tid] && oi < ba[tid])) { bm[tid] = ov; ba[tid] = oi; }
            }
            __syncthreads();
        }
        if (tid == 0) {
            g_max = bm[0];
            g_arg = ba[0];
            __threadfence();
            atomicExch(&g_flag, 1);
        }
    }

    // ---- grid-wide wait for g_max
    if (tid == 0) {
        while (atomicAdd(&g_flag, 0) == 0) { __nanosleep(64); }
    }
    __syncthreads();
    float gm = *((volatile float*)&g_max);

    // ---- phase 2: Z = sum e^(s-max), S = sum e^(s-max) * s  (double)
    __shared__ double zb[256];
    __shared__ double sb[256];
    double gmd = (double)gm;
    double z = 0.0, ssum = 0.0;
    for (int i = blockIdx.x * 256 + tid; i < N; i += nb * 256) {
        double v = (double)g_scores[i];
        double e = exp(v - gmd);
        z += e; ssum += e * v;
    }
    zb[tid] = z; sb[tid] = ssum;
    __syncthreads();
    for (int s = 128; s > 0; s >>= 1) {
        if (tid < s) { zb[tid] += zb[tid + s]; sb[tid] += sb[tid + s]; }
        __syncthreads();
    }
    if (tid == 0) {
        atomicAdd(&g_Z, zb[0]);
        atomicAdd(&g_S, sb[0]);
        __threadfence();
        unsigned t = atomicAdd(&g_cnt2, 1u);
        if (t == (unsigned)(nb - 1)) {
            double Z = atomicAdd(&g_Z, 0.0);
            double S = atomicAdd(&g_S, 0.0);
            double logZ = log(Z);
            int    arg  = *((volatile int*)&g_arg);
            float  mx   = *((volatile float*)&g_max);
            out[0] = (float)arg;                          // idx
            out[1] = (float)exp(-logZ);                   // probs[idx]
            out[2] = (float)(-logZ);                      // logp[idx]
            out[3] = (float)((double)mx + logZ - S / Z);  // entropy
        }
    }
}

// ---------------- launch ---------------------------------------------------
extern "C" void kernel_launch(void* const* d_in, const int* in_sizes, int n_in,
                              void* d_out, int out_size) {
    const float* xg   = (const float*)d_in[0];
    const float* xm   = (const float*)d_in[1];
    const float* xj   = (const float*)d_in[2];
    const int*   mids = (const int*)  d_in[3];
    const int*   jidx = (const int*)  d_in[4];
    const float* W0   = (const float*)d_in[5];
    const float* b0   = (const float*)d_in[6];
    const float* W1   = (const float*)d_in[7];
    const float* b1   = (const float*)d_in[8];
    const float* W2   = (const float*)d_in[9];
    const float* b2   = (const float*)d_in[10];
    float* out = (float*)d_out;

    int N = in_sizes[3];
    int M = in_sizes[1] / HD;
    int J = in_sizes[2] / HD;
    if (N > N_MAX) N = N_MAX;
    if (M > M_MAX) M = M_MAX;
    if (J > J_MAX) J = J_MAX;

    const int pre_smem  = (16384 + 8 * 128) * 4;             // 69632 B
    const int main_smem = (16384 + 8192 + 3 * 128) * 4;      // 99840 B
    cudaFuncSetAttribute(k_pre,  cudaFuncAttributeMaxDynamicSharedMemorySize, pre_smem);
    cudaFuncSetAttribute(k_main, cudaFuncAttributeMaxDynamicSharedMemorySize, main_smem);

    int bM = (M + 7) / 8, bJ = (J + 7) / 8;
    k_pre<<<bM + bJ + 1, 128, pre_smem>>>(xg, xm, xj, W0, b0, M, J);
    k_main<<<296, 256, main_smem>>>(mids, jidx, W1, b1, W2, b2, N);
    k_reduce<<<148, 256>>>(out, N);
    (void)n_in; (void)out_size;
}